// round 2
// baseline (speedup 1.0000x reference)
#include <cuda_runtime.h>

// Problem constants
#define B   32
#define DE  256
#define T   32
#define C   128
#define HW  16384   // 128*128

// Scratch for the projected embeddings e_ : [B][C][T]
__device__ float g_e[B * C * T];

// Packed dual-FP32 FMA (sm_103a): d = a*b + c componentwise.
__device__ __forceinline__ float2 ffma2(float2 a, float2 b, float2 c) {
    unsigned long long ua = *reinterpret_cast<unsigned long long*>(&a);
    unsigned long long ub = *reinterpret_cast<unsigned long long*>(&b);
    unsigned long long uc = *reinterpret_cast<unsigned long long*>(&c);
    unsigned long long ud;
    asm("fma.rn.f32x2 %0, %1, %2, %3;" : "=l"(ud) : "l"(ua), "l"(ub), "l"(uc));
    return *reinterpret_cast<float2*>(&ud);
}

// ---------------------------------------------------------------------------
// Kernel 1: e_[b][c][t] = sum_d e[b][d][t] * Wd[d][c] + bias[c]
// grid (16, 32), block 128. Each thread: one c, one t-pair (2 t's).
// ---------------------------------------------------------------------------
__global__ __launch_bounds__(128)
void proj_kernel(const float* __restrict__ e,
                 const float* __restrict__ Wd,
                 const float* __restrict__ bias) {
    __shared__ float e_sm[DE * T];  // 32 KB, [d][t]
    const int b = blockIdx.y;

    const float4* e4  = reinterpret_cast<const float4*>(e + b * DE * T);
    float4*       es4 = reinterpret_cast<float4*>(e_sm);
#pragma unroll
    for (int i = 0; i < DE * T / 4 / 128; i++)
        es4[i * 128 + threadIdx.x] = e4[i * 128 + threadIdx.x];
    __syncthreads();

    const int c  = blockIdx.x * 8 + (threadIdx.x >> 4);
    const int t0 = (threadIdx.x & 15) * 2;

    float2 acc = make_float2(0.0f, 0.0f);
#pragma unroll 8
    for (int d = 0; d < DE; d++) {
        const float w = __ldg(&Wd[d * C + c]);
        const float2 ev = *reinterpret_cast<const float2*>(e_sm + d * T + t0);
        acc = ffma2(make_float2(w, w), ev, acc);
    }

    const float bc = bias[c];
    float2* outp = reinterpret_cast<float2*>(g_e + (b * C + c) * T + t0);
    *outp = make_float2(acc.x + bc, acc.y + bc);
}

// ---------------------------------------------------------------------------
// Kernel 2: fused scores + softmax + context + concat.
// grid (HW/512, B), block 128 (4 warps). Each warp owns 128 pixels; each lane
// owns 4 adjacent pixels. s/beta live t-packed as float2 in registers, so the
// softmax over T=32 is fully lane-local. The h->out copy is fused into the
// score loop (h is loaded exactly once).
// ---------------------------------------------------------------------------

// Accumulate one channel into the t-packed score accumulators (all 4 pixels).
#define SCH(ch, x0, x1, x2, x3) do {                                           \
    const float2 hA = make_float2((x0), (x0));                                 \
    const float2 hB = make_float2((x1), (x1));                                 \
    const float2 hC = make_float2((x2), (x2));                                 \
    const float2 hD = make_float2((x3), (x3));                                 \
    const float4* er_ = reinterpret_cast<const float4*>(e_sm + (ch) * T);      \
    _Pragma("unroll")                                                          \
    for (int j4 = 0; j4 < 8; j4++) {                                           \
        const float4 ev = er_[j4];                                             \
        const float2 e0 = make_float2(ev.x, ev.y);                             \
        const float2 e1 = make_float2(ev.z, ev.w);                             \
        s0[2 * j4]     = ffma2(hA, e0, s0[2 * j4]);                            \
        s0[2 * j4 + 1] = ffma2(hA, e1, s0[2 * j4 + 1]);                        \
        s1[2 * j4]     = ffma2(hB, e0, s1[2 * j4]);                            \
        s1[2 * j4 + 1] = ffma2(hB, e1, s1[2 * j4 + 1]);                        \
        s2[2 * j4]     = ffma2(hC, e0, s2[2 * j4]);                            \
        s2[2 * j4 + 1] = ffma2(hC, e1, s2[2 * j4 + 1]);                        \
        s3[2 * j4]     = ffma2(hD, e0, s3[2 * j4]);                            \
        s3[2 * j4 + 1] = ffma2(hD, e1, s3[2 * j4 + 1]);                        \
    }                                                                          \
} while (0)

// Lane-local softmax (unnormalized exp; returns 1/sum) for one pixel.
#define SOFTMAX1(s, inv) do {                                                  \
    float2 m2 = s[0];                                                          \
    _Pragma("unroll")                                                          \
    for (int j = 1; j < 16; j++) {                                             \
        m2.x = fmaxf(m2.x, s[j].x);                                            \
        m2.y = fmaxf(m2.y, s[j].y);                                            \
    }                                                                          \
    const float m = fmaxf(m2.x, m2.y);                                         \
    float2 sum = make_float2(0.0f, 0.0f);                                      \
    _Pragma("unroll")                                                          \
    for (int j = 0; j < 16; j++) {                                             \
        s[j].x = __expf(s[j].x - m);                                           \
        s[j].y = __expf(s[j].y - m);                                           \
        sum.x += s[j].x;                                                       \
        sum.y += s[j].y;                                                       \
    }                                                                          \
    inv = 1.0f / (sum.x + sum.y);                                              \
} while (0)

__global__ __launch_bounds__(128, 2)
void attn_kernel(const float* __restrict__ h, float* __restrict__ out) {
    __shared__ float e_sm[C * T];  // 16 KB, [c][t]

    const int b     = blockIdx.y;
    const int pbase = blockIdx.x * 512;
    const int tid   = threadIdx.x;

    // Stage e_ for this batch (broadcast-read later).
    {
        const float4* ge4 = reinterpret_cast<const float4*>(g_e + b * C * T);
        float4*       es4 = reinterpret_cast<float4*>(e_sm);
#pragma unroll
        for (int i = 0; i < C * T / 4 / 128; i++)
            es4[i * 128 + tid] = ge4[i * 128 + tid];
    }
    __syncthreads();

    const int warp = tid >> 5;
    const int lane = tid & 31;
    const int p0   = pbase + warp * 128 + lane * 4;  // this lane's 4 pixels

    const float4* hp = reinterpret_cast<const float4*>(h + (b * HW + p0) * C);
    float4*       op = reinterpret_cast<float4*>(out + (b * HW + p0) * 2 * C);

    // ---- Phase 1: scores s[t] for 4 pixels (t-packed float2 x16 each),
    //      with the h->out copy fused in. ----
    float2 s0[16], s1[16], s2[16], s3[16];
#pragma unroll
    for (int j = 0; j < 16; j++) {
        s0[j] = make_float2(0.0f, 0.0f);
        s1[j] = make_float2(0.0f, 0.0f);
        s2[j] = make_float2(0.0f, 0.0f);
        s3[j] = make_float2(0.0f, 0.0f);
    }

#pragma unroll 2
    for (int cc = 0; cc < 32; cc++) {  // 32 chunks of 4 channels
        const float4 ha = hp[0 * 32 + cc];
        const float4 hb = hp[1 * 32 + cc];
        const float4 hc = hp[2 * 32 + cc];
        const float4 hd = hp[3 * 32 + cc];
        // fused concat copy: out[..., C:2C] = h
        op[0 * 64 + 32 + cc] = ha;
        op[1 * 64 + 32 + cc] = hb;
        op[2 * 64 + 32 + cc] = hc;
        op[3 * 64 + 32 + cc] = hd;
        const int ch = cc * 4;
        SCH(ch + 0, ha.x, hb.x, hc.x, hd.x);
        SCH(ch + 1, ha.y, hb.y, hc.y, hd.y);
        SCH(ch + 2, ha.z, hb.z, hc.z, hd.z);
        SCH(ch + 3, ha.w, hb.w, hc.w, hd.w);
    }

    // ---- Phase 2: lane-local softmax over T for each pixel ----
    float inv0, inv1, inv2, inv3;
    SOFTMAX1(s0, inv0);
    SOFTMAX1(s1, inv1);
    SOFTMAX1(s2, inv2);
    SOFTMAX1(s3, inv3);

    // ---- Phase 3: context c[ch] = sum_t e_[ch][t] * beta[t], 4 pixels ----
#pragma unroll 1
    for (int g = 0; g < 32; g++) {  // 4 output channels per group -> float4
        float4 r0, r1, r2, r3;
        float* r0p = reinterpret_cast<float*>(&r0);
        float* r1p = reinterpret_cast<float*>(&r1);
        float* r2p = reinterpret_cast<float*>(&r2);
        float* r3p = reinterpret_cast<float*>(&r3);
#pragma unroll
        for (int k = 0; k < 4; k++) {
            const int ch = g * 4 + k;
            const float4* er = reinterpret_cast<const float4*>(e_sm + ch * T);
            float2 a0 = make_float2(0.0f, 0.0f);
            float2 a1 = make_float2(0.0f, 0.0f);
            float2 a2 = make_float2(0.0f, 0.0f);
            float2 a3 = make_float2(0.0f, 0.0f);
#pragma unroll
            for (int j4 = 0; j4 < 8; j4++) {
                const float4 ev = er[j4];
                const float2 e0 = make_float2(ev.x, ev.y);
                const float2 e1 = make_float2(ev.z, ev.w);
                a0 = ffma2(e0, s0[2 * j4], a0);
                a0 = ffma2(e1, s0[2 * j4 + 1], a0);
                a1 = ffma2(e0, s1[2 * j4], a1);
                a1 = ffma2(e1, s1[2 * j4 + 1], a1);
                a2 = ffma2(e0, s2[2 * j4], a2);
                a2 = ffma2(e1, s2[2 * j4 + 1], a2);
                a3 = ffma2(e0, s3[2 * j4], a3);
                a3 = ffma2(e1, s3[2 * j4 + 1], a3);
            }
            r0p[k] = (a0.x + a0.y) * inv0;
            r1p[k] = (a1.x + a1.y) * inv1;
            r2p[k] = (a2.x + a2.y) * inv2;
            r3p[k] = (a3.x + a3.y) * inv3;
        }
        op[0 * 64 + g] = r0;
        op[1 * 64 + g] = r1;
        op[2 * 64 + g] = r2;
        op[3 * 64 + g] = r3;
    }
}

// ---------------------------------------------------------------------------
extern "C" void kernel_launch(void* const* d_in, const int* in_sizes, int n_in,
                              void* d_out, int out_size) {
    const float* e    = (const float*)d_in[0];  // [B, DE, T]
    const float* h    = (const float*)d_in[1];  // [B, H, W, C]
    const float* Wd   = (const float*)d_in[2];  // [DE, C]
    const float* bias = (const float*)d_in[3];  // [C]
    float* out = (float*)d_out;                 // [B, H, W, 2C]

    proj_kernel<<<dim3(16, B), 128>>>(e, Wd, bias);
    attn_kernel<<<dim3(HW / 512, B), 128>>>(h, out);
}

// round 5
// speedup vs baseline: 1.7787x; 1.7787x over previous
#include <cuda_runtime.h>
#include <cuda_bf16.h>
#include <cstdint>
#include <cstring>

// Problem constants
#define B   32
#define DE  256
#define T   32
#define C   128
#define HW  16384   // 128*128

// ===========================================================================
// Warp-level MMA helpers (plain sm_80+ PTX: ldmatrix + mma.sync bf16 -> HMMA)
// ===========================================================================
__device__ __forceinline__ void ldsm4(uint32_t& r0, uint32_t& r1,
                                      uint32_t& r2, uint32_t& r3, uint32_t addr) {
    asm volatile("ldmatrix.sync.aligned.m8n8.x4.shared.b16 {%0,%1,%2,%3}, [%4];"
                 : "=r"(r0), "=r"(r1), "=r"(r2), "=r"(r3) : "r"(addr));
}

__device__ __forceinline__ void mma_bf16(float& d0, float& d1, float& d2, float& d3,
                                         uint32_t a0, uint32_t a1, uint32_t a2, uint32_t a3,
                                         uint32_t b0, uint32_t b1) {
    asm volatile(
        "mma.sync.aligned.m16n8k16.row.col.f32.bf16.bf16.f32 "
        "{%0,%1,%2,%3}, {%4,%5,%6,%7}, {%8,%9}, {%0,%1,%2,%3};"
        : "+f"(d0), "+f"(d1), "+f"(d2), "+f"(d3)
        : "r"(a0), "r"(a1), "r"(a2), "r"(a3), "r"(b0), "r"(b1));
}

__device__ __forceinline__ uint32_t smem_to_u32(const void* smem_ptr) {
    uint32_t addr;
    asm("{ .reg .u64 tmp; cvta.to.shared.u64 tmp, %1; cvt.u32.u64 %0, tmp; }"
        : "=r"(addr) : "l"(smem_ptr));
    return addr;
}

__device__ __forceinline__ uint32_t pack2(__nv_bfloat16 lo, __nv_bfloat16 hi) {
    __nv_bfloat162 v; v.x = lo; v.y = hi;   // .x = lower K index
    uint32_t u; memcpy(&u, &v, 4);
    return u;
}

__device__ __forceinline__ void split_bf16(float x, __nv_bfloat16& hi, __nv_bfloat16& lo) {
    hi = __float2bfloat16_rn(x);
    lo = __float2bfloat16_rn(x - __bfloat162float(hi));
}

// ===========================================================================
// Global scratch: e_ in bf16 hi/lo splits, both orientations.
//   g_eS_*: [B][T][C]  (B operand of score GEMM; K = channels, contiguous)
//   g_eC_*: [B][C][T]  (B operand of context GEMM; K = t, contiguous)
// ===========================================================================
__device__ __nv_bfloat16 g_eS_hi[B * T * C];
__device__ __nv_bfloat16 g_eS_lo[B * T * C];
__device__ __nv_bfloat16 g_eC_hi[B * C * T];
__device__ __nv_bfloat16 g_eC_lo[B * C * T];

// ---------------------------------------------------------------------------
// Prep kernel: e_[c][t] = sum_d e[b][d][t]*Wd[d][c] + bias[c] (fp32 accum),
// split into bf16 hi/lo in both orientations. grid (2,B), block 256.
// ---------------------------------------------------------------------------
__global__ __launch_bounds__(256)
void prep_kernel(const float* __restrict__ e,
                 const float* __restrict__ Wd,
                 const float* __restrict__ bias) {
    __shared__ float e_sm[DE * T];  // 32 KB, [d][t]
    const int b = blockIdx.y;

    const float4* e4  = reinterpret_cast<const float4*>(e + b * DE * T);
    float4*       es4 = reinterpret_cast<float4*>(e_sm);
#pragma unroll
    for (int i = 0; i < DE * T / 4 / 256; i++)
        es4[i * 256 + threadIdx.x] = e4[i * 256 + threadIdx.x];
    __syncthreads();

    const int c  = blockIdx.x * 64 + (threadIdx.x >> 2);
    const int t0 = (threadIdx.x & 3) * 8;

    float acc[8];
#pragma unroll
    for (int i = 0; i < 8; i++) acc[i] = 0.0f;

#pragma unroll 4
    for (int d = 0; d < DE; d++) {
        const float w = __ldg(&Wd[d * C + c]);
        const float4* er = reinterpret_cast<const float4*>(e_sm + d * T + t0);
        const float4 v0 = er[0];
        const float4 v1 = er[1];
        acc[0] = fmaf(w, v0.x, acc[0]);
        acc[1] = fmaf(w, v0.y, acc[1]);
        acc[2] = fmaf(w, v0.z, acc[2]);
        acc[3] = fmaf(w, v0.w, acc[3]);
        acc[4] = fmaf(w, v1.x, acc[4]);
        acc[5] = fmaf(w, v1.y, acc[5]);
        acc[6] = fmaf(w, v1.z, acc[6]);
        acc[7] = fmaf(w, v1.w, acc[7]);
    }

    const float bc = bias[c];
#pragma unroll
    for (int i = 0; i < 8; i++) {
        const int t = t0 + i;
        const float x = acc[i] + bc;
        __nv_bfloat16 hi, lo;
        split_bf16(x, hi, lo);
        g_eS_hi[(b * T + t) * C + c] = hi;
        g_eS_lo[(b * T + t) * C + c] = lo;
        g_eC_hi[(b * C + c) * T + t] = hi;
        g_eC_lo[(b * C + c) * T + t] = lo;
    }
}

// ---------------------------------------------------------------------------
// Fused attention kernel: 128-pixel tile per block, 256 threads (8 warps),
// each warp owns 16 pixels (one m16 MMA row-tile).
//   S[16px,32t]  = h[16,128] . e_S[32,128]^T   (bf16 split-2, 3 passes, HMMA)
//   softmax over t: 4-lane shuffle reduction; beta stays in MMA A-fragments
//   Ctx[16px,128c] = beta[16,32] . e_C[128,32]^T (split-2, 3 passes)
// h -> out[...,C:2C] copy fused into the h load.
// ---------------------------------------------------------------------------

// Padded smem strides (bytes): 272 = 17*16 units, 80 = 5*16 -> LDSM conflict-free.
#define STR_HC  272
#define STR_EC  80

#define SH_H_HI  0                  // 128 x 272 = 34816
#define SH_H_LO  34816              // 34816
#define SH_ES_HI 69632              // 32 x 272 = 8704
#define SH_ES_LO 78336              // 8704
#define SH_EC_HI 87040              // 128 x 80 = 10240
#define SH_EC_LO 97280              // 10240
#define SMEM_TOTAL 107520

__global__ __launch_bounds__(256, 2)
void attn_kernel(const float* __restrict__ h, float* __restrict__ out) {
    extern __shared__ char smem[];
    const uint32_t sbase = smem_to_u32(smem);

    const int tid  = threadIdx.x;
    const int warp = tid >> 5;
    const int lane = tid & 31;
    const int b    = blockIdx.y;
    const int p0   = blockIdx.x * 128;

    // ---- Stage e_S tiles ([t][c] bf16, hi+lo), padded rows ----
    {
        const uint32_t* eh = reinterpret_cast<const uint32_t*>(g_eS_hi + b * T * C);
        const uint32_t* el = reinterpret_cast<const uint32_t*>(g_eS_lo + b * T * C);
#pragma unroll
        for (int i0 = 0; i0 < 8; i0++) {          // 2048 pairs / 256 threads
            const int i  = i0 * 256 + tid;
            const int t  = i >> 6;
            const int cp = i & 63;
            const uint32_t off = (uint32_t)(t * STR_HC + cp * 4);
            *reinterpret_cast<uint32_t*>(smem + SH_ES_HI + off) = eh[i];
            *reinterpret_cast<uint32_t*>(smem + SH_ES_LO + off) = el[i];
        }
    }
    // ---- Stage e_C tiles ([c][t] bf16, hi+lo) ----
    {
        const uint32_t* eh = reinterpret_cast<const uint32_t*>(g_eC_hi + b * C * T);
        const uint32_t* el = reinterpret_cast<const uint32_t*>(g_eC_lo + b * C * T);
#pragma unroll
        for (int i0 = 0; i0 < 8; i0++) {          // 2048 pairs / 256 threads
            const int i  = i0 * 256 + tid;
            const int c  = i >> 4;
            const int tp = i & 15;
            const uint32_t off = (uint32_t)(c * STR_EC + tp * 4);
            *reinterpret_cast<uint32_t*>(smem + SH_EC_HI + off) = eh[i];
            *reinterpret_cast<uint32_t*>(smem + SH_EC_LO + off) = el[i];
        }
    }
    // ---- Load h tile (128px x 128c fp32): fused concat copy + bf16 split ----
    {
        const float4* hp = reinterpret_cast<const float4*>(h + (size_t)(b * HW + p0) * C);
        float4*       op = reinterpret_cast<float4*>(out + (size_t)(b * HW + p0) * 2 * C);
#pragma unroll 4
        for (int j = 0; j < 16; j++) {            // 4096 float4 / 256 threads
            const int idx = j * 256 + tid;
            const int px  = idx >> 5;
            const int c4  = idx & 31;
            const float4 v = hp[idx];
            op[px * 64 + 32 + c4] = v;            // out[...,C:2C] = h

            __nv_bfloat16 h0, h1, h2, h3, l0, l1, l2, l3;
            split_bf16(v.x, h0, l0);
            split_bf16(v.y, h1, l1);
            split_bf16(v.z, h2, l2);
            split_bf16(v.w, h3, l3);
            const uint32_t off = (uint32_t)(px * STR_HC + c4 * 8);
            *reinterpret_cast<uint32_t*>(smem + SH_H_HI + off)     = pack2(h0, h1);
            *reinterpret_cast<uint32_t*>(smem + SH_H_HI + off + 4) = pack2(h2, h3);
            *reinterpret_cast<uint32_t*>(smem + SH_H_LO + off)     = pack2(l0, l1);
            *reinterpret_cast<uint32_t*>(smem + SH_H_LO + off + 4) = pack2(l2, l3);
        }
    }
    __syncthreads();

    // Per-lane LDSM address components
    const uint32_t aRow  = (uint32_t)(lane & 15);
    const uint32_t aCol  = (uint32_t)((lane >> 4) * 16);
    const uint32_t bRow  = (uint32_t)(8 * (lane >> 4) + (lane & 7));
    const uint32_t bCol  = (uint32_t)(((lane >> 3) & 1) * 16);

    // ---- Score GEMM: S[16,32] in 4 n-tiles of m16n8 fragments ----
    float sd[4][4];
#pragma unroll
    for (int nt = 0; nt < 4; nt++)
#pragma unroll
        for (int q = 0; q < 4; q++) sd[nt][q] = 0.0f;

    {
        const uint32_t aBase = sbase + SH_H_HI + (uint32_t)(warp * 16) * STR_HC
                             + aRow * STR_HC + aCol;
        const uint32_t bBase = sbase + SH_ES_HI + bRow * STR_HC + bCol;
#pragma unroll
        for (int k = 0; k < 8; k++) {             // K=128 in steps of 16
            const uint32_t aAddr = aBase + (uint32_t)(k * 32);
            const uint32_t bAddr = bBase + (uint32_t)(k * 32);
            uint32_t aH[4], aL[4], bH[8], bL[8];
            ldsm4(aH[0], aH[1], aH[2], aH[3], aAddr);
            ldsm4(aL[0], aL[1], aL[2], aL[3], aAddr + (SH_H_LO - SH_H_HI));
            ldsm4(bH[0], bH[1], bH[2], bH[3], bAddr);                    // t 0-15
            ldsm4(bH[4], bH[5], bH[6], bH[7], bAddr + 16 * STR_HC);      // t 16-31
            ldsm4(bL[0], bL[1], bL[2], bL[3], bAddr + (SH_ES_LO - SH_ES_HI));
            ldsm4(bL[4], bL[5], bL[6], bL[7], bAddr + (SH_ES_LO - SH_ES_HI) + 16 * STR_HC);
#pragma unroll
            for (int nt = 0; nt < 4; nt++) {
                const uint32_t bh0 = bH[nt * 2], bh1 = bH[nt * 2 + 1];
                const uint32_t bl0 = bL[nt * 2], bl1 = bL[nt * 2 + 1];
                mma_bf16(sd[nt][0], sd[nt][1], sd[nt][2], sd[nt][3],
                         aH[0], aH[1], aH[2], aH[3], bh0, bh1);          // hi*hi
                mma_bf16(sd[nt][0], sd[nt][1], sd[nt][2], sd[nt][3],
                         aL[0], aL[1], aL[2], aL[3], bh0, bh1);          // lo*hi
                mma_bf16(sd[nt][0], sd[nt][1], sd[nt][2], sd[nt][3],
                         aH[0], aH[1], aH[2], aH[3], bl0, bl1);          // hi*lo
            }
        }
    }

    // ---- Softmax over t (rows r=lane/4 and r+8; 8 values per row per lane,
    //      full row spread across the 4 lanes sharing lane/4) ----
    float er[8], eh8[8];
#pragma unroll
    for (int nt = 0; nt < 4; nt++) {
        er[2 * nt]      = sd[nt][0];
        er[2 * nt + 1]  = sd[nt][1];
        eh8[2 * nt]     = sd[nt][2];
        eh8[2 * nt + 1] = sd[nt][3];
    }
    float m0 = er[0], m1 = eh8[0];
#pragma unroll
    for (int i = 1; i < 8; i++) { m0 = fmaxf(m0, er[i]); m1 = fmaxf(m1, eh8[i]); }
    m0 = fmaxf(m0, __shfl_xor_sync(0xFFFFFFFFu, m0, 1));
    m0 = fmaxf(m0, __shfl_xor_sync(0xFFFFFFFFu, m0, 2));
    m1 = fmaxf(m1, __shfl_xor_sync(0xFFFFFFFFu, m1, 1));
    m1 = fmaxf(m1, __shfl_xor_sync(0xFFFFFFFFu, m1, 2));

    float s0 = 0.0f, s1 = 0.0f;
#pragma unroll
    for (int i = 0; i < 8; i++) {
        er[i]  = __expf(er[i] - m0);  s0 += er[i];
        eh8[i] = __expf(eh8[i] - m1); s1 += eh8[i];
    }
    s0 += __shfl_xor_sync(0xFFFFFFFFu, s0, 1);
    s0 += __shfl_xor_sync(0xFFFFFFFFu, s0, 2);
    s1 += __shfl_xor_sync(0xFFFFFFFFu, s1, 1);
    s1 += __shfl_xor_sync(0xFFFFFFFFu, s1, 2);
    const float inv0 = 1.0f / s0;
    const float inv1 = 1.0f / s1;
#pragma unroll
    for (int i = 0; i < 8; i++) { er[i] *= inv0; eh8[i] *= inv1; }

    // Beta directly as MMA A fragments (k = t), hi/lo split, 2 k-steps.
    uint32_t bAH[2][4], bAL[2][4];
#pragma unroll
    for (int ks = 0; ks < 2; ks++) {
        const int base = ks * 4;
        __nv_bfloat16 h0, h1, l0, l1;
        split_bf16(er[base], h0, l0);  split_bf16(er[base + 1], h1, l1);
        bAH[ks][0] = pack2(h0, h1);    bAL[ks][0] = pack2(l0, l1);
        split_bf16(eh8[base], h0, l0); split_bf16(eh8[base + 1], h1, l1);
        bAH[ks][1] = pack2(h0, h1);    bAL[ks][1] = pack2(l0, l1);
        split_bf16(er[base + 2], h0, l0);  split_bf16(er[base + 3], h1, l1);
        bAH[ks][2] = pack2(h0, h1);    bAL[ks][2] = pack2(l0, l1);
        split_bf16(eh8[base + 2], h0, l0); split_bf16(eh8[base + 3], h1, l1);
        bAH[ks][3] = pack2(h0, h1);    bAL[ks][3] = pack2(l0, l1);
    }

    // ---- Context GEMM: Ctx[16,128] in 4 chunks of 32 channels ----
    const int pxr = p0 + warp * 16 + (lane >> 2);
    const int tg  = lane & 3;
    float* outB = out + (size_t)(b * HW) * 2 * C;

#pragma unroll
    for (int chunk = 0; chunk < 4; chunk++) {
        float cd[4][4];
#pragma unroll
        for (int nt = 0; nt < 4; nt++)
#pragma unroll
            for (int q = 0; q < 4; q++) cd[nt][q] = 0.0f;

#pragma unroll
        for (int ks = 0; ks < 2; ks++) {
            const uint32_t bAddr = sbase + SH_EC_HI
                + (uint32_t)(chunk * 32 + bRow) * STR_EC + bCol + (uint32_t)(ks * 32);
            uint32_t bH[8], bL[8];
            ldsm4(bH[0], bH[1], bH[2], bH[3], bAddr);                    // c-tiles 0,1
            ldsm4(bH[4], bH[5], bH[6], bH[7], bAddr + 16 * STR_EC);      // c-tiles 2,3
            ldsm4(bL[0], bL[1], bL[2], bL[3], bAddr + (SH_EC_LO - SH_EC_HI));
            ldsm4(bL[4], bL[5], bL[6], bL[7], bAddr + (SH_EC_LO - SH_EC_HI) + 16 * STR_EC);
#pragma unroll
            for (int nt = 0; nt < 4; nt++) {
                const uint32_t bh0 = bH[nt * 2], bh1 = bH[nt * 2 + 1];
                const uint32_t bl0 = bL[nt * 2], bl1 = bL[nt * 2 + 1];
                mma_bf16(cd[nt][0], cd[nt][1], cd[nt][2], cd[nt][3],
                         bAH[ks][0], bAH[ks][1], bAH[ks][2], bAH[ks][3], bh0, bh1);
                mma_bf16(cd[nt][0], cd[nt][1], cd[nt][2], cd[nt][3],
                         bAL[ks][0], bAL[ks][1], bAL[ks][2], bAL[ks][3], bh0, bh1);
                mma_bf16(cd[nt][0], cd[nt][1], cd[nt][2], cd[nt][3],
                         bAH[ks][0], bAH[ks][1], bAH[ks][2], bAH[ks][3], bl0, bl1);
            }
        }

        // Store: ctx goes to out[px][0:C]
#pragma unroll
        for (int nt = 0; nt < 4; nt++) {
            const int c = chunk * 32 + nt * 8 + 2 * tg;
            float2* q0 = reinterpret_cast<float2*>(outB + (size_t)pxr * 2 * C + c);
            float2* q1 = reinterpret_cast<float2*>(outB + (size_t)(pxr + 8) * 2 * C + c);
            *q0 = make_float2(cd[nt][0], cd[nt][1]);
            *q1 = make_float2(cd[nt][2], cd[nt][3]);
        }
    }
}

// ---------------------------------------------------------------------------
extern "C" void kernel_launch(void* const* d_in, const int* in_sizes, int n_in,
                              void* d_out, int out_size) {
    const float* e    = (const float*)d_in[0];  // [B, DE, T]
    const float* h    = (const float*)d_in[1];  // [B, H, W, C]
    const float* Wd   = (const float*)d_in[2];  // [DE, C]
    const float* bias = (const float*)d_in[3];  // [C]
    float* out = (float*)d_out;                 // [B, H, W, 2C]

    cudaFuncSetAttribute(attn_kernel,
                         cudaFuncAttributeMaxDynamicSharedMemorySize, SMEM_TOTAL);

    prep_kernel<<<dim3(2, B), 256>>>(e, Wd, bias);
    attn_kernel<<<dim3(HW / 128, B), 256, SMEM_TOTAL>>>(h, out);
}

// round 6
// speedup vs baseline: 1.9833x; 1.1150x over previous
#include <cuda_runtime.h>
#include <cuda_bf16.h>
#include <cstdint>
#include <cstring>

// Problem constants
#define B   32
#define DE  256
#define T   32
#define C   128
#define HW  16384   // 128*128

// ===========================================================================
// Helpers
// ===========================================================================
__device__ __forceinline__ void ldsm4(uint32_t& r0, uint32_t& r1,
                                      uint32_t& r2, uint32_t& r3, uint32_t addr) {
    asm volatile("ldmatrix.sync.aligned.m8n8.x4.shared.b16 {%0,%1,%2,%3}, [%4];"
                 : "=r"(r0), "=r"(r1), "=r"(r2), "=r"(r3) : "r"(addr));
}

__device__ __forceinline__ void mma_bf16(float& d0, float& d1, float& d2, float& d3,
                                         uint32_t a0, uint32_t a1, uint32_t a2, uint32_t a3,
                                         uint32_t b0, uint32_t b1) {
    asm volatile(
        "mma.sync.aligned.m16n8k16.row.col.f32.bf16.bf16.f32 "
        "{%0,%1,%2,%3}, {%4,%5,%6,%7}, {%8,%9}, {%0,%1,%2,%3};"
        : "+f"(d0), "+f"(d1), "+f"(d2), "+f"(d3)
        : "r"(a0), "r"(a1), "r"(a2), "r"(a3), "r"(b0), "r"(b1));
}

__device__ __forceinline__ uint32_t smem_to_u32(const void* smem_ptr) {
    uint32_t addr;
    asm("{ .reg .u64 tmp; cvta.to.shared.u64 tmp, %1; cvt.u32.u64 %0, tmp; }"
        : "=r"(addr) : "l"(smem_ptr));
    return addr;
}

__device__ __forceinline__ float2 ffma2(float2 a, float2 b, float2 c) {
    unsigned long long ua, ub, uc, ud;
    memcpy(&ua, &a, 8); memcpy(&ub, &b, 8); memcpy(&uc, &c, 8);
    asm("fma.rn.f32x2 %0, %1, %2, %3;" : "=l"(ud) : "l"(ua), "l"(ub), "l"(uc));
    float2 d; memcpy(&d, &ud, 8);
    return d;
}

__device__ __forceinline__ uint32_t pack2(__nv_bfloat16 lo, __nv_bfloat16 hi) {
    __nv_bfloat162 v; v.x = lo; v.y = hi;   // .x = lower K index
    uint32_t u; memcpy(&u, &v, 4);
    return u;
}

__device__ __forceinline__ void split_bf16(float x, __nv_bfloat16& hi, __nv_bfloat16& lo) {
    hi = __float2bfloat16_rn(x);
    lo = __float2bfloat16_rn(x - __bfloat162float(hi));
}

#define CP_ASYNC16(dst, src) \
    asm volatile("cp.async.cg.shared.global [%0], [%1], 16;" \
                 :: "r"(dst), "l"(src) : "memory")
#define CP_ASYNC_COMMIT() asm volatile("cp.async.commit_group;" ::: "memory")
#define CP_ASYNC_WAIT0()  asm volatile("cp.async.wait_group 0;" ::: "memory")

// ===========================================================================
// Global scratch: e_ in bf16 hi/lo splits, both orientations.
//   g_eS_*: [B][T][C]  (B operand of score GEMM; K = channels, contiguous)
//   g_eC_*: [B][C][T]  (B operand of context GEMM; K = t, contiguous)
// ===========================================================================
__device__ __nv_bfloat16 g_eS_hi[B * T * C];
__device__ __nv_bfloat16 g_eS_lo[B * T * C];
__device__ __nv_bfloat16 g_eC_hi[B * C * T];
__device__ __nv_bfloat16 g_eC_lo[B * C * T];

// ---------------------------------------------------------------------------
// Prep kernel: e_[c][t] = sum_d e[b][d][t]*Wd[d][c] + bias[c] (fp32 accum),
// split into bf16 hi/lo in both orientations. grid (4,B), block 256.
// Thread mapping: c = bx*32 + (tid&31) -> Wd reads are 128B-coalesced and
// L1-broadcast across the 8 warps; t0 = (tid>>5)*4.
// ---------------------------------------------------------------------------
__global__ __launch_bounds__(256)
void prep_kernel(const float* __restrict__ e,
                 const float* __restrict__ Wd,
                 const float* __restrict__ bias) {
    __shared__ float e_sm[DE * T];  // 32 KB, [d][t]
    const int b   = blockIdx.y;
    const int tid = threadIdx.x;

    const float4* e4  = reinterpret_cast<const float4*>(e + b * DE * T);
    float4*       es4 = reinterpret_cast<float4*>(e_sm);
#pragma unroll
    for (int i = 0; i < DE * T / 4 / 256; i++)
        es4[i * 256 + tid] = e4[i * 256 + tid];
    __syncthreads();

    const int c  = blockIdx.x * 32 + (tid & 31);
    const int t0 = (tid >> 5) * 4;

    float2 acc0 = make_float2(0.f, 0.f), acc1 = make_float2(0.f, 0.f);
#pragma unroll 8
    for (int d = 0; d < DE; d++) {
        const float w = __ldg(&Wd[d * C + c]);
        const float4 ev = *reinterpret_cast<const float4*>(e_sm + d * T + t0);
        const float2 w2 = make_float2(w, w);
        acc0 = ffma2(w2, make_float2(ev.x, ev.y), acc0);
        acc1 = ffma2(w2, make_float2(ev.z, ev.w), acc1);
    }

    const float bc = bias[c];
    float xs[4] = { acc0.x + bc, acc0.y + bc, acc1.x + bc, acc1.y + bc };
#pragma unroll
    for (int i = 0; i < 4; i++) {
        const int t = t0 + i;
        __nv_bfloat16 hi, lo;
        split_bf16(xs[i], hi, lo);
        g_eS_hi[(b * T + t) * C + c] = hi;
        g_eS_lo[(b * T + t) * C + c] = lo;
        g_eC_hi[(b * C + c) * T + t] = hi;
        g_eC_lo[(b * C + c) * T + t] = lo;
    }
}

// ---------------------------------------------------------------------------
// Fused attention kernel: 128-pixel tile per block, 256 threads (8 warps),
// each warp owns 16 pixels (one m16 MMA row-tile).
//   S[16px,32t]  = h[16,128] . e_S[32,128]^T   (bf16 split-2, 3 passes, HMMA)
//   softmax over t: 4-lane shuffle reduction; beta stays in MMA A-fragments
//   Ctx[16px,128c] = beta[16,32] . e_C[128,32]^T (split-2, 3 passes)
// h -> out[...,C:2C] copy fused into the h load; eS/eC staged via cp.async.
// ---------------------------------------------------------------------------

// Padded smem strides (bytes): 272 = 17*16 units, 80 = 5*16 -> LDSM conflict-free.
#define STR_HC  272
#define STR_EC  80

#define SH_H_HI  0                  // 128 x 272 = 34816
#define SH_H_LO  34816              // 34816
#define SH_ES_HI 69632              // 32 x 272 = 8704
#define SH_ES_LO 78336              // 8704
#define SH_EC_HI 87040              // 128 x 80 = 10240
#define SH_EC_LO 97280              // 10240
#define SMEM_TOTAL 107520

__global__ __launch_bounds__(256, 2)
void attn_kernel(const float* __restrict__ h, float* __restrict__ out) {
    extern __shared__ char smem[];
    const uint32_t sbase = smem_to_u32(smem);

    const int tid  = threadIdx.x;
    const int warp = tid >> 5;
    const int lane = tid & 31;
    const int b    = blockIdx.y;
    const int p0   = blockIdx.x * 128;

    // ---- Async-stage e_S tiles ([t][c] bf16, hi+lo), 16B chunks ----
    {
        const char* ehS = reinterpret_cast<const char*>(g_eS_hi + b * T * C);
        const char* elS = reinterpret_cast<const char*>(g_eS_lo + b * T * C);
#pragma unroll
        for (int i = 0; i < 2; i++) {             // 512 chunks / 256 threads
            const int idx = i * 256 + tid;
            const int t   = idx >> 4;
            const int c16 = idx & 15;
            const uint32_t dst = sbase + (uint32_t)(t * STR_HC + c16 * 16);
            const int      src = t * 256 + c16 * 16;   // bytes within tile
            CP_ASYNC16(dst + SH_ES_HI, ehS + src);
            CP_ASYNC16(dst + SH_ES_LO, elS + src);
        }
    }
    // ---- Async-stage e_C tiles ([c][t] bf16, hi+lo) ----
    {
        const char* ehC = reinterpret_cast<const char*>(g_eC_hi + b * C * T);
        const char* elC = reinterpret_cast<const char*>(g_eC_lo + b * C * T);
#pragma unroll
        for (int i = 0; i < 2; i++) {             // 512 chunks / 256 threads
            const int idx = i * 256 + tid;
            const int c   = idx >> 2;
            const int u   = idx & 3;
            const uint32_t dst = sbase + (uint32_t)(c * STR_EC + u * 16);
            const int      src = c * 64 + u * 16;      // bytes within tile
            CP_ASYNC16(dst + SH_EC_HI, ehC + src);
            CP_ASYNC16(dst + SH_EC_LO, elC + src);
        }
    }
    CP_ASYNC_COMMIT();

    // ---- Load h tile (128px x 128c fp32): fused concat copy + bf16 split ----
    {
        const float4* hp = reinterpret_cast<const float4*>(h + (size_t)(b * HW + p0) * C);
        float4*       op = reinterpret_cast<float4*>(out + (size_t)(b * HW + p0) * 2 * C);
#pragma unroll 8
        for (int j = 0; j < 16; j++) {            // 4096 float4 / 256 threads
            const int idx = j * 256 + tid;
            const int px  = idx >> 5;
            const int c4  = idx & 31;
            const float4 v = hp[idx];
            op[px * 64 + 32 + c4] = v;            // out[...,C:2C] = h

            __nv_bfloat16 h0, h1, h2, h3, l0, l1, l2, l3;
            split_bf16(v.x, h0, l0);
            split_bf16(v.y, h1, l1);
            split_bf16(v.z, h2, l2);
            split_bf16(v.w, h3, l3);
            const uint32_t off = (uint32_t)(px * STR_HC + c4 * 8);
            *reinterpret_cast<uint32_t*>(smem + SH_H_HI + off)     = pack2(h0, h1);
            *reinterpret_cast<uint32_t*>(smem + SH_H_HI + off + 4) = pack2(h2, h3);
            *reinterpret_cast<uint32_t*>(smem + SH_H_LO + off)     = pack2(l0, l1);
            *reinterpret_cast<uint32_t*>(smem + SH_H_LO + off + 4) = pack2(l2, l3);
        }
    }
    CP_ASYNC_WAIT0();
    __syncthreads();

    // Per-lane LDSM address components
    const uint32_t aRow  = (uint32_t)(lane & 15);
    const uint32_t aCol  = (uint32_t)((lane >> 4) * 16);
    const uint32_t bRow  = (uint32_t)(8 * (lane >> 4) + (lane & 7));
    const uint32_t bCol  = (uint32_t)(((lane >> 3) & 1) * 16);

    // ---- Score GEMM: S[16,32] in 4 n-tiles of m16n8 fragments ----
    float sd[4][4];
#pragma unroll
    for (int nt = 0; nt < 4; nt++)
#pragma unroll
        for (int q = 0; q < 4; q++) sd[nt][q] = 0.0f;

    {
        const uint32_t aBase = sbase + SH_H_HI + (uint32_t)(warp * 16) * STR_HC
                             + aRow * STR_HC + aCol;
        const uint32_t bBase = sbase + SH_ES_HI + bRow * STR_HC + bCol;
#pragma unroll
        for (int k = 0; k < 8; k++) {             // K=128 in steps of 16
            const uint32_t aAddr = aBase + (uint32_t)(k * 32);
            const uint32_t bAddr = bBase + (uint32_t)(k * 32);
            uint32_t aH[4], aL[4], bH[8], bL[8];
            ldsm4(aH[0], aH[1], aH[2], aH[3], aAddr);
            ldsm4(aL[0], aL[1], aL[2], aL[3], aAddr + (SH_H_LO - SH_H_HI));
            ldsm4(bH[0], bH[1], bH[2], bH[3], bAddr);                    // t 0-15
            ldsm4(bH[4], bH[5], bH[6], bH[7], bAddr + 16 * STR_HC);      // t 16-31
            ldsm4(bL[0], bL[1], bL[2], bL[3], bAddr + (SH_ES_LO - SH_ES_HI));
            ldsm4(bL[4], bL[5], bL[6], bL[7], bAddr + (SH_ES_LO - SH_ES_HI) + 16 * STR_HC);
#pragma unroll
            for (int nt = 0; nt < 4; nt++) {
                const uint32_t bh0 = bH[nt * 2], bh1 = bH[nt * 2 + 1];
                const uint32_t bl0 = bL[nt * 2], bl1 = bL[nt * 2 + 1];
                mma_bf16(sd[nt][0], sd[nt][1], sd[nt][2], sd[nt][3],
                         aH[0], aH[1], aH[2], aH[3], bh0, bh1);          // hi*hi
                mma_bf16(sd[nt][0], sd[nt][1], sd[nt][2], sd[nt][3],
                         aL[0], aL[1], aL[2], aL[3], bh0, bh1);          // lo*hi
                mma_bf16(sd[nt][0], sd[nt][1], sd[nt][2], sd[nt][3],
                         aH[0], aH[1], aH[2], aH[3], bl0, bl1);          // hi*lo
            }
        }
    }

    // ---- Softmax over t (rows r=lane/4 and r+8; full row spread across the
    //      4 lanes sharing lane/4) ----
    float er[8], eh8[8];
#pragma unroll
    for (int nt = 0; nt < 4; nt++) {
        er[2 * nt]      = sd[nt][0];
        er[2 * nt + 1]  = sd[nt][1];
        eh8[2 * nt]     = sd[nt][2];
        eh8[2 * nt + 1] = sd[nt][3];
    }
    float m0 = er[0], m1 = eh8[0];
#pragma unroll
    for (int i = 1; i < 8; i++) { m0 = fmaxf(m0, er[i]); m1 = fmaxf(m1, eh8[i]); }
    m0 = fmaxf(m0, __shfl_xor_sync(0xFFFFFFFFu, m0, 1));
    m0 = fmaxf(m0, __shfl_xor_sync(0xFFFFFFFFu, m0, 2));
    m1 = fmaxf(m1, __shfl_xor_sync(0xFFFFFFFFu, m1, 1));
    m1 = fmaxf(m1, __shfl_xor_sync(0xFFFFFFFFu, m1, 2));

    float s0 = 0.0f, s1 = 0.0f;
#pragma unroll
    for (int i = 0; i < 8; i++) {
        er[i]  = __expf(er[i] - m0);  s0 += er[i];
        eh8[i] = __expf(eh8[i] - m1); s1 += eh8[i];
    }
    s0 += __shfl_xor_sync(0xFFFFFFFFu, s0, 1);
    s0 += __shfl_xor_sync(0xFFFFFFFFu, s0, 2);
    s1 += __shfl_xor_sync(0xFFFFFFFFu, s1, 1);
    s1 += __shfl_xor_sync(0xFFFFFFFFu, s1, 2);
    const float inv0 = 1.0f / s0;
    const float inv1 = 1.0f / s1;
#pragma unroll
    for (int i = 0; i < 8; i++) { er[i] *= inv0; eh8[i] *= inv1; }

    // Beta directly as MMA A fragments (k = t), hi/lo split, 2 k-steps.
    uint32_t bAH[2][4], bAL[2][4];
#pragma unroll
    for (int ks = 0; ks < 2; ks++) {
        const int base = ks * 4;
        __nv_bfloat16 h0, h1, l0, l1;
        split_bf16(er[base], h0, l0);  split_bf16(er[base + 1], h1, l1);
        bAH[ks][0] = pack2(h0, h1);    bAL[ks][0] = pack2(l0, l1);
        split_bf16(eh8[base], h0, l0); split_bf16(eh8[base + 1], h1, l1);
        bAH[ks][1] = pack2(h0, h1);    bAL[ks][1] = pack2(l0, l1);
        split_bf16(er[base + 2], h0, l0);  split_bf16(er[base + 3], h1, l1);
        bAH[ks][2] = pack2(h0, h1);    bAL[ks][2] = pack2(l0, l1);
        split_bf16(eh8[base + 2], h0, l0); split_bf16(eh8[base + 3], h1, l1);
        bAH[ks][3] = pack2(h0, h1);    bAL[ks][3] = pack2(l0, l1);
    }

    // ---- Context GEMM: Ctx[16,128] in 4 chunks of 32 channels ----
    const int pxr = p0 + warp * 16 + (lane >> 2);
    const int tg  = lane & 3;
    float* outB = out + (size_t)(b * HW) * 2 * C;

#pragma unroll
    for (int chunk = 0; chunk < 4; chunk++) {
        float cd[4][4];
#pragma unroll
        for (int nt = 0; nt < 4; nt++)
#pragma unroll
            for (int q = 0; q < 4; q++) cd[nt][q] = 0.0f;

#pragma unroll
        for (int ks = 0; ks < 2; ks++) {
            const uint32_t bAddr = sbase + SH_EC_HI
                + (uint32_t)(chunk * 32 + bRow) * STR_EC + bCol + (uint32_t)(ks * 32);
            uint32_t bH[8], bL[8];
            ldsm4(bH[0], bH[1], bH[2], bH[3], bAddr);                    // c-tiles 0,1
            ldsm4(bH[4], bH[5], bH[6], bH[7], bAddr + 16 * STR_EC);      // c-tiles 2,3
            ldsm4(bL[0], bL[1], bL[2], bL[3], bAddr + (SH_EC_LO - SH_EC_HI));
            ldsm4(bL[4], bL[5], bL[6], bL[7], bAddr + (SH_EC_LO - SH_EC_HI) + 16 * STR_EC);
#pragma unroll
            for (int nt = 0; nt < 4; nt++) {
                const uint32_t bh0 = bH[nt * 2], bh1 = bH[nt * 2 + 1];
                const uint32_t bl0 = bL[nt * 2], bl1 = bL[nt * 2 + 1];
                mma_bf16(cd[nt][0], cd[nt][1], cd[nt][2], cd[nt][3],
                         bAH[ks][0], bAH[ks][1], bAH[ks][2], bAH[ks][3], bh0, bh1);
                mma_bf16(cd[nt][0], cd[nt][1], cd[nt][2], cd[nt][3],
                         bAL[ks][0], bAL[ks][1], bAL[ks][2], bAL[ks][3], bh0, bh1);
                mma_bf16(cd[nt][0], cd[nt][1], cd[nt][2], cd[nt][3],
                         bAH[ks][0], bAH[ks][1], bAH[ks][2], bAH[ks][3], bl0, bl1);
            }
        }

        // Store: ctx goes to out[px][0:C]
#pragma unroll
        for (int nt = 0; nt < 4; nt++) {
            const int c = chunk * 32 + nt * 8 + 2 * tg;
            float2* q0 = reinterpret_cast<float2*>(outB + (size_t)pxr * 2 * C + c);
            float2* q1 = reinterpret_cast<float2*>(outB + (size_t)(pxr + 8) * 2 * C + c);
            *q0 = make_float2(cd[nt][0], cd[nt][1]);
            *q1 = make_float2(cd[nt][2], cd[nt][3]);
        }
    }
}

// ---------------------------------------------------------------------------
extern "C" void kernel_launch(void* const* d_in, const int* in_sizes, int n_in,
                              void* d_out, int out_size) {
    const float* e    = (const float*)d_in[0];  // [B, DE, T]
    const float* h    = (const float*)d_in[1];  // [B, H, W, C]
    const float* Wd   = (const float*)d_in[2];  // [DE, C]
    const float* bias = (const float*)d_in[3];  // [C]
    float* out = (float*)d_out;                 // [B, H, W, 2C]

    cudaFuncSetAttribute(attn_kernel,
                         cudaFuncAttributeMaxDynamicSharedMemorySize, SMEM_TOTAL);

    prep_kernel<<<dim3(4, B), 256>>>(e, Wd, bias);
    attn_kernel<<<dim3(HW / 128, B), 256, SMEM_TOTAL>>>(h, out);
}